// round 12
// baseline (speedup 1.0000x reference)
#include <cuda_runtime.h>
#include <cooperative_groups.h>

namespace cg = cooperative_groups;

#define BATCH   64
#define NGT     1024
#define MPRED   2048
#define THRESH2 256.0f    // 16.0^2
#define GDIM    32        // 32x32 grid of 16px cells (512 / 16)
#define NCELL   (GDIM * GDIM)

// Cluster of 2 CTAs (1024 threads) per batch; grid = 128. Each CTA bins the
// batch's 1024 gts into a 32x32 cell CSR in its own smem, then scans 1024
// preds (rank r -> preds [r*1024, ...)) against the 3x3 cell neighborhood —
// exactly equivalent to the full argmin (matches only matter under the 16px
// threshold; any gt within 16px lies in the 3x3 neighborhood). Both ranks
// atomicMin (gt -> min pred index) into RANK 0's s_best (DSMEM for rank 1);
// cluster.sync(); rank 0 gathers from an smem-staged pred slab.
//
// R11: (d2, gi) lexicographic argmin as ONE u64 min over
// key = (d2_bits << 32) | gi (d2 >= 0 so IEEE bits order as unsigned).
// Init key bits(256)<<32 folds the threshold (strict <, first-index ties).
//
// R12: the scan processes 2 candidates per iteration with packed f32x2 math:
// dx = add.rn.f32x2({q0x,q1x}, {-px,-px}) etc. The sign flip (q-p vs p-q)
// is erased by the square — (q-p)^2 == (p-q)^2 bit-exactly — and per-lane
// .rn packed ops are bit-identical to scalar, so d2 bits are unchanged.
// Halves loop-control overhead and the warp-divergence union iteration
// count. Scalar epilogue covers odd run lengths.
__global__ __launch_bounds__(1024, 1) __cluster_dims__(2, 1, 1)
void lacss_match_kernel(
    const float2* __restrict__ gt,    // [BATCH, NGT]
    const float2* __restrict__ pred,  // [BATCH, MPRED]
    float2* __restrict__ out)         // [BATCH, NGT]
{
    __shared__ int    s_cnt[NCELL];      // counts, then scatter cursor
    __shared__ int    s_off[NCELL + 1];  // exclusive CSR offsets
    __shared__ float4 s_pt[NGT];         // {gx, gy, idx-as-float, pad} binned
    __shared__ int    s_best[NGT];       // min matched pred j per gt (rank0 authoritative)
    __shared__ float2 s_pred[MPRED];     // full pred slab (rank0 authoritative)
    __shared__ int    s_wsum[32];

    cg::cluster_group cluster = cg::this_cluster();
    const unsigned rank = cluster.block_rank();

    const int b    = blockIdx.x >> 1;
    const int tid  = threadIdx.x;
    const int lane = tid & 31;
    const int wid  = tid >> 5;

    // ---- prefetch both inputs (MLP=2, DRAM latency behind binning) ----
    const int j = (int)rank * 1024 + tid;          // this thread's pred
    const float2 p = pred[b * MPRED + j];
    const float2 g = gt[b * NGT + tid];

    s_cnt[tid]  = 0;
    s_best[tid] = MPRED;                 // sentinel: unmatched
    __syncthreads();

    // ---- stage pred slab into rank0's smem (overlapped with binning) ----
    {
        float2* dst = (rank == 0) ? s_pred
                                  : cluster.map_shared_rank(s_pred, 0);
        dst[j] = p;                      // disjoint ranges per rank
    }

    // ---- count (cell = y/16 * 32 + x/16; *2^-4 exact) ----
    const int gcell = (int)(g.y * 0.0625f) * GDIM + (int)(g.x * 0.0625f);
    atomicAdd(&s_cnt[gcell], 1);
    __syncthreads();

    // ---- exclusive prefix sum of s_cnt -> s_off ----
    int v   = s_cnt[tid];
    int inc = v;
    #pragma unroll
    for (int d = 1; d < 32; d <<= 1) {
        int n = __shfl_up_sync(0xFFFFFFFFu, inc, d);
        if (lane >= d) inc += n;
    }
    if (lane == 31) s_wsum[wid] = inc;
    __syncthreads();
    if (wid == 0) {
        int w  = s_wsum[lane];
        int wi = w;
        #pragma unroll
        for (int d = 1; d < 32; d <<= 1) {
            int n = __shfl_up_sync(0xFFFFFFFFu, wi, d);
            if (lane >= d) wi += n;
        }
        s_wsum[lane] = wi - w;           // exclusive offset of warp `lane`
    }
    __syncthreads();
    const int excl = (inc - v) + s_wsum[wid];
    s_off[tid] = excl;
    if (tid == 0) s_off[NCELL] = NGT;
    s_cnt[tid] = excl;                   // cursor = copy of offsets
    __syncthreads();

    // ---- scatter gts into binned order, original idx packed into .z ----
    {
        int pos = atomicAdd(&s_cnt[gcell], 1);
        s_pt[pos] = make_float4(g.x, g.y, __int_as_float(tid), 0.f);
    }
    __syncthreads();

    // ---- pred phase: 3x3 neighborhood, 2 candidates/iteration ----
    {
        const int pcx = (int)(p.x * 0.0625f);
        const int pcy = (int)(p.y * 0.0625f);
        const int x0 = max(pcx - 1, 0), x1 = min(pcx + 1, GDIM - 1);
        const int y0 = max(pcy - 1, 0), y1 = min(pcy + 1, GDIM - 1);

        // pre-packed {-px,-px}, {-py,-py}
        unsigned long long npx2, npy2;
        {
            unsigned int nx = __float_as_uint(-p.x);
            unsigned int ny = __float_as_uint(-p.y);
            asm("mov.b64 %0, {%1, %1};" : "=l"(npx2) : "r"(nx));
            asm("mov.b64 %0, {%1, %1};" : "=l"(npy2) : "r"(ny));
        }

        const unsigned long long K0 =
            ((unsigned long long)__float_as_uint(THRESH2)) << 32;
        unsigned long long best = K0;

        for (int cy = y0; cy <= y1; cy++) {
            int k        = s_off[cy * GDIM + x0];
            const int ke = s_off[cy * GDIM + x1 + 1];   // cells contiguous in x

            // paired iterations: 2 candidates per pass, packed f32x2 math
            for (; k + 1 < ke; k += 2) {
                float4 a = s_pt[k];
                float4 c = s_pt[k + 1];
                unsigned long long qx2, qy2, dx2, dy2, xx, yy, d2;
                asm("mov.b64 %0, {%1, %2};" : "=l"(qx2)
                    : "r"(__float_as_uint(a.x)), "r"(__float_as_uint(c.x)));
                asm("mov.b64 %0, {%1, %2};" : "=l"(qy2)
                    : "r"(__float_as_uint(a.y)), "r"(__float_as_uint(c.y)));
                asm("add.rn.f32x2 %0, %1, %2;" : "=l"(dx2) : "l"(qx2), "l"(npx2));
                asm("add.rn.f32x2 %0, %1, %2;" : "=l"(dy2) : "l"(qy2), "l"(npy2));
                asm("mul.rn.f32x2 %0, %1, %1;" : "=l"(xx) : "l"(dx2));
                asm("mul.rn.f32x2 %0, %1, %1;" : "=l"(yy) : "l"(dy2));
                asm("add.rn.f32x2 %0, %1, %2;" : "=l"(d2) : "l"(xx), "l"(yy));
                unsigned int d0, d1;
                asm("mov.b64 {%0, %1}, %2;" : "=r"(d0), "=r"(d1) : "l"(d2));
                unsigned long long key0, key1;
                asm("mov.b64 %0, {%1, %2};" : "=l"(key0)
                    : "r"((unsigned int)__float_as_int(a.z)), "r"(d0));
                asm("mov.b64 %0, {%1, %2};" : "=l"(key1)
                    : "r"((unsigned int)__float_as_int(c.z)), "r"(d1));
                best = (key0 < best) ? key0 : best;
                best = (key1 < best) ? key1 : best;
            }
            // scalar epilogue for odd run length
            if (k < ke) {
                float4 q = s_pt[k];
                float dx = __fadd_rn(p.x, -q.x);
                float dy = __fadd_rn(p.y, -q.y);
                float d2s = __fadd_rn(__fmul_rn(dx, dx), __fmul_rn(dy, dy));
                unsigned long long key;
                asm("mov.b64 %0, {%1, %2};" : "=l"(key)
                    : "r"((unsigned int)__float_as_int(q.z)),
                      "r"(__float_as_uint(d2s)));
                best = (key < best) ? key : best;
            }
        }

        if (best < K0) {
            int bi = (int)(unsigned int)best;           // low word = gt index
            int* dst = (rank == 0) ? s_best
                                   : cluster.map_shared_rank(s_best, 0);
            atomicMin(&dst[bi], j);
        }
    }

    cluster.sync();                      // orders remote atomics + s_pred stores

    // ---- fused gather by rank 0: pure-SMEM reads ----
    if (rank == 0) {
        const int s = s_best[tid];
        out[b * NGT + tid] = (s < MPRED) ? s_pred[s] : g;
    }
}

extern "C" void kernel_launch(void* const* d_in, const int* in_sizes, int n_in,
                              void* d_out, int out_size) {
    const float2* gt   = (const float2*)d_in[0];   // gt_locations   [64,1024,2] f32
    const float2* pred = (const float2*)d_in[1];   // pred_locations [64,2048,2] f32
    float2* out = (float2*)d_out;                  // [64,1024,2] f32

    lacss_match_kernel<<<BATCH * 2, 1024>>>(gt, pred, out);
}

// round 13
// speedup vs baseline: 1.0240x; 1.0240x over previous
#include <cuda_runtime.h>

#define BATCH   64
#define NGT     1024
#define MPRED   2048
#define THRESH2 256.0f    // 16.0^2
#define GDIM    32        // 32x32 grid of 16px cells (512 / 16)
#define NCELL   (GDIM * GDIM)

// Per-(batch, gt): max over matching preds of (MPRED - j) == MPRED - min_j.
// Sentinel 0 = unmatched. Zero-initialized at load; the gathering CTA resets
// its batch's slots to 0 after reading, so every launch (graph replay) sees
// all-zero scratch. g_cnt: per-batch arrival counter, same reset discipline.
__device__ int      g_best[BATCH * NGT];
__device__ unsigned g_cnt[BATCH];

// 128 independent CTAs (2 per batch), 1024 threads, NO cluster. Each CTA bins
// the batch's 1024 gts into a 32x32-cell CSR in smem, scans its 1024 preds
// (rank r -> [r*1024, ...)) against the 3x3 cell neighborhood — exactly
// equivalent to the full argmin (matches only matter under the 16px
// threshold; any gt within 16px lies in the 3x3 neighborhood). Matches
// publish via fire-and-forget red.global.max (no return, ~1cyc/lane) instead
// of 215-cyc DSMEM atomics. Cross-CTA dependency: last-arriver-gathers via a
// per-batch counter with release/acquire fences. Whichever CTA gathers, the
// output is identical (max over disjoint j-sets) -> deterministic.
//
// Scan argmin: ONE u64 min over key = (d2_bits << 32) | gi (d2 >= 0 so IEEE
// bits order as unsigned); init key bits(256)<<32 folds the threshold
// (strict <, first-index tie rule of jnp.argmin). d2 via __fadd_rn/__fmul_rn
// (no FMA) -> bit-identical to the reference.
__global__ __launch_bounds__(1024, 1) void lacss_match_kernel(
    const float2* __restrict__ gt,    // [BATCH, NGT]
    const float2* __restrict__ pred,  // [BATCH, MPRED]
    float2* __restrict__ out)         // [BATCH, NGT]
{
    __shared__ int    s_cnt[NCELL];      // counts, then scatter cursor
    __shared__ int    s_off[NCELL + 1];  // exclusive CSR offsets
    __shared__ float4 s_pt[NGT];         // {gx, gy, idx-as-float, pad} binned
    __shared__ int    s_wsum[32];
    __shared__ int    s_last;            // am I the gathering CTA?

    const int rank = blockIdx.x & 1;
    const int b    = blockIdx.x >> 1;
    const int tid  = threadIdx.x;
    const int lane = tid & 31;
    const int wid  = tid >> 5;

    // ---- prefetch both inputs (MLP=2, DRAM latency behind binning) ----
    const int j = rank * 1024 + tid;               // this thread's pred
    const float2 p = pred[b * MPRED + j];
    const float2 g = gt[b * NGT + tid];

    s_cnt[tid] = 0;
    __syncthreads();

    // ---- count (cell = y/16 * 32 + x/16; *2^-4 exact) ----
    const int gcell = (int)(g.y * 0.0625f) * GDIM + (int)(g.x * 0.0625f);
    atomicAdd(&s_cnt[gcell], 1);
    __syncthreads();

    // ---- exclusive prefix sum of s_cnt -> s_off ----
    int v   = s_cnt[tid];
    int inc = v;
    #pragma unroll
    for (int d = 1; d < 32; d <<= 1) {
        int n = __shfl_up_sync(0xFFFFFFFFu, inc, d);
        if (lane >= d) inc += n;
    }
    if (lane == 31) s_wsum[wid] = inc;
    __syncthreads();
    if (wid == 0) {
        int w  = s_wsum[lane];
        int wi = w;
        #pragma unroll
        for (int d = 1; d < 32; d <<= 1) {
            int n = __shfl_up_sync(0xFFFFFFFFu, wi, d);
            if (lane >= d) wi += n;
        }
        s_wsum[lane] = wi - w;           // exclusive offset of warp `lane`
    }
    __syncthreads();
    const int excl = (inc - v) + s_wsum[wid];
    s_off[tid] = excl;
    if (tid == 0) s_off[NCELL] = NGT;
    s_cnt[tid] = excl;                   // cursor = copy of offsets
    __syncthreads();

    // ---- scatter gts into binned order, original idx packed into .z ----
    {
        int pos = atomicAdd(&s_cnt[gcell], 1);
        s_pt[pos] = make_float4(g.x, g.y, __int_as_float(tid), 0.f);
    }
    __syncthreads();

    // ---- pred phase: one pred per thread, 3x3 neighborhood (3 runs) ----
    {
        const int pcx = (int)(p.x * 0.0625f);
        const int pcy = (int)(p.y * 0.0625f);
        const int x0 = max(pcx - 1, 0), x1 = min(pcx + 1, GDIM - 1);
        const int y0 = max(pcy - 1, 0), y1 = min(pcy + 1, GDIM - 1);

        const unsigned long long K0 =
            ((unsigned long long)__float_as_uint(THRESH2)) << 32;
        unsigned long long best = K0;

        for (int cy = y0; cy <= y1; cy++) {
            const int ks = s_off[cy * GDIM + x0];
            const int ke = s_off[cy * GDIM + x1 + 1];   // cells contiguous in x
            for (int k = ks; k < ke; k++) {
                float4 q = s_pt[k];                     // one LDS.128
                float dx = __fadd_rn(p.x, -q.x);
                float dy = __fadd_rn(p.y, -q.y);
                float d2 = __fadd_rn(__fmul_rn(dx, dx), __fmul_rn(dy, dy));
                unsigned long long key;
                asm("mov.b64 %0, {%1, %2};" : "=l"(key)
                    : "r"((unsigned int)__float_as_int(q.z)),
                      "r"(__float_as_uint(d2)));
                best = (key < best) ? key : best;
            }
        }

        if (best < K0) {
            int bi = (int)(unsigned int)best;           // low word = gt index
            // fire-and-forget global reduction, no return value
            asm volatile("red.global.max.s32 [%0], %1;"
                         :: "l"(&g_best[b * NGT + bi]), "r"(MPRED - j)
                         : "memory");
        }
    }

    // ---- last-CTA-arrives protocol ----
    __syncthreads();                     // all this CTA's REDs are prior to tid0's fence
    if (tid == 0) {
        asm volatile("fence.acq_rel.gpu;" ::: "memory");   // release our REDs
        unsigned old = atomicAdd(&g_cnt[b], 1u);
        asm volatile("fence.acq_rel.gpu;" ::: "memory");   // acquire peer's REDs
        s_last = (old == 1);
    }
    __syncthreads();                     // propagates tid0's acquire to all threads
    if (!s_last) return;                 // first arriver exits; second gathers

    // ---- gather + reset (scratch back to all-zero for next replay) ----
    {
        const int idx = b * NGT + tid;
        const int s = __ldcg(&g_best[idx]);  // L2 read (bypass L1)
        out[idx] = (s > 0) ? pred[b * MPRED + (MPRED - s)] : g;
        g_best[idx] = 0;
        if (tid == 0) g_cnt[b] = 0;
    }
}

extern "C" void kernel_launch(void* const* d_in, const int* in_sizes, int n_in,
                              void* d_out, int out_size) {
    const float2* gt   = (const float2*)d_in[0];   // gt_locations   [64,1024,2] f32
    const float2* pred = (const float2*)d_in[1];   // pred_locations [64,2048,2] f32
    float2* out = (float2*)d_out;                  // [64,1024,2] f32

    lacss_match_kernel<<<BATCH * 2, 1024>>>(gt, pred, out);
}

// round 14
// speedup vs baseline: 1.0270x; 1.0030x over previous
#include <cuda_runtime.h>
#include <cooperative_groups.h>

namespace cg = cooperative_groups;

#define BATCH   64
#define NGT     1024
#define MPRED   2048
#define THRESH2 256.0f    // 16.0^2
#define GDIM    32        // 32x32 grid of 16px cells (512 / 16)
#define NCELL   (GDIM * GDIM)

// FINAL (R11 structure, best measured: 10.24us total / 9.50us kernel).
//
// Cluster of 2 CTAs (1024 threads) per batch; grid = 128. Each CTA bins the
// batch's 1024 gts into a 32x32 cell CSR in its own smem, then scans 1024
// preds (rank r -> preds [r*1024, ...)) against the 3x3 cell neighborhood —
// exactly equivalent to the full argmin (matches only matter under the 16px
// threshold, and any gt within 16px of a pred lies in the 3x3 neighborhood
// of the pred's cell). Both ranks atomicMin (gt -> min pred index) into
// RANK 0's s_best (DSMEM atomic for rank 1); cluster.sync(); rank 0 gathers
// from an smem-staged pred slab.
//
// Argmin: ONE u64 min over key = (d2_bits << 32) | gi — valid because
// d2 >= 0 so IEEE bits order as unsigned ints. Init key = bits(256.0f)<<32
// folds the threshold: any d2 < 256 beats it for every gi; d2 >= 256 never
// does (strict <, matching the reference). Min gi within min d2 =
// jnp.argmin first-index tie rule, order-invariant.
//
// d2 uses __fadd_rn/__fmul_rn (no FMA contraction) -> bit-identical to the
// reference's mul-then-add; rel_err is exactly 0.0.
__global__ __launch_bounds__(1024, 1) __cluster_dims__(2, 1, 1)
void lacss_match_kernel(
    const float2* __restrict__ gt,    // [BATCH, NGT]
    const float2* __restrict__ pred,  // [BATCH, MPRED]
    float2* __restrict__ out)         // [BATCH, NGT]
{
    __shared__ int    s_cnt[NCELL];      // counts, then scatter cursor
    __shared__ int    s_off[NCELL + 1];  // exclusive CSR offsets
    __shared__ float4 s_pt[NGT];         // {gx, gy, idx-as-float, pad} binned
    __shared__ int    s_best[NGT];       // min matched pred j per gt (rank0 authoritative)
    __shared__ float2 s_pred[MPRED];     // full pred slab (rank0 authoritative)
    __shared__ int    s_wsum[32];

    cg::cluster_group cluster = cg::this_cluster();
    const unsigned rank = cluster.block_rank();

    const int b    = blockIdx.x >> 1;
    const int tid  = threadIdx.x;
    const int lane = tid & 31;
    const int wid  = tid >> 5;

    // ---- prefetch both inputs (MLP=2, DRAM latency behind binning) ----
    const int j = (int)rank * 1024 + tid;          // this thread's pred
    const float2 p = pred[b * MPRED + j];
    const float2 g = gt[b * NGT + tid];

    s_cnt[tid]  = 0;
    s_best[tid] = MPRED;                 // sentinel: unmatched
    __syncthreads();

    // ---- stage pred slab into rank0's smem (overlapped with binning;
    //      visibility at the tail via cluster.sync) ----
    {
        float2* dst = (rank == 0) ? s_pred
                                  : cluster.map_shared_rank(s_pred, 0);
        dst[j] = p;                      // disjoint ranges per rank
    }

    // ---- count (cell = y/16 * 32 + x/16; *2^-4 exact) ----
    const int gcell = (int)(g.y * 0.0625f) * GDIM + (int)(g.x * 0.0625f);
    atomicAdd(&s_cnt[gcell], 1);
    __syncthreads();

    // ---- exclusive prefix sum of s_cnt -> s_off ----
    int v   = s_cnt[tid];
    int inc = v;
    #pragma unroll
    for (int d = 1; d < 32; d <<= 1) {
        int n = __shfl_up_sync(0xFFFFFFFFu, inc, d);
        if (lane >= d) inc += n;
    }
    if (lane == 31) s_wsum[wid] = inc;
    __syncthreads();
    if (wid == 0) {
        int w  = s_wsum[lane];
        int wi = w;
        #pragma unroll
        for (int d = 1; d < 32; d <<= 1) {
            int n = __shfl_up_sync(0xFFFFFFFFu, wi, d);
            if (lane >= d) wi += n;
        }
        s_wsum[lane] = wi - w;           // exclusive offset of warp `lane`
    }
    __syncthreads();
    const int excl = (inc - v) + s_wsum[wid];
    s_off[tid] = excl;
    if (tid == 0) s_off[NCELL] = NGT;
    s_cnt[tid] = excl;                   // cursor = copy of offsets
    __syncthreads();

    // ---- scatter gts into binned order, original idx packed into .z ----
    {
        int pos = atomicAdd(&s_cnt[gcell], 1);
        s_pt[pos] = make_float4(g.x, g.y, __int_as_float(tid), 0.f);
    }
    __syncthreads();

    // ---- pred phase: one pred per thread, 3x3 neighborhood (3 runs),
    //      selection = single u64 min over (d2_bits, gi) ----
    {
        const int pcx = (int)(p.x * 0.0625f);
        const int pcy = (int)(p.y * 0.0625f);
        const int x0 = max(pcx - 1, 0), x1 = min(pcx + 1, GDIM - 1);
        const int y0 = max(pcy - 1, 0), y1 = min(pcy + 1, GDIM - 1);

        const unsigned long long K0 =
            ((unsigned long long)__float_as_uint(THRESH2)) << 32;
        unsigned long long best = K0;

        for (int cy = y0; cy <= y1; cy++) {
            const int ks = s_off[cy * GDIM + x0];
            const int ke = s_off[cy * GDIM + x1 + 1];   // cells contiguous in x
            for (int k = ks; k < ke; k++) {
                float4 q = s_pt[k];                     // one LDS.128
                float dx = __fadd_rn(p.x, -q.x);
                float dy = __fadd_rn(p.y, -q.y);
                float d2 = __fadd_rn(__fmul_rn(dx, dx), __fmul_rn(dy, dy));
                unsigned int bits = __float_as_uint(d2);
                unsigned int gi   = (unsigned int)__float_as_int(q.z);
                unsigned long long key;
                asm("mov.b64 %0, {%1, %2};" : "=l"(key) : "r"(gi), "r"(bits));
                best = (key < best) ? key : best;
            }
        }

        if (best < K0) {
            int bi = (int)(unsigned int)best;           // low word = gt index
            int* dst = (rank == 0) ? s_best
                                   : cluster.map_shared_rank(s_best, 0);
            atomicMin(&dst[bi], j);
        }
    }

    cluster.sync();                      // orders remote atomics + s_pred stores

    // ---- fused gather by rank 0: pure-SMEM reads ----
    if (rank == 0) {
        const int s = s_best[tid];
        out[b * NGT + tid] = (s < MPRED) ? s_pred[s] : g;
    }
}

extern "C" void kernel_launch(void* const* d_in, const int* in_sizes, int n_in,
                              void* d_out, int out_size) {
    const float2* gt   = (const float2*)d_in[0];   // gt_locations   [64,1024,2] f32
    const float2* pred = (const float2*)d_in[1];   // pred_locations [64,2048,2] f32
    float2* out = (float2*)d_out;                  // [64,1024,2] f32

    lacss_match_kernel<<<BATCH * 2, 1024>>>(gt, pred, out);
}

// round 15
// speedup vs baseline: 1.0556x; 1.0278x over previous
#include <cuda_runtime.h>
#include <cooperative_groups.h>

namespace cg = cooperative_groups;

#define BATCH   64
#define NGT     1024
#define MPRED   2048
#define THRESH2 256.0f    // 16.0^2
#define GDIM    32        // 32x32 grid of 16px cells (512 / 16)
#define NCELL   (GDIM * GDIM)

// Cluster of 2 CTAs (1024 threads) per batch; grid = 128. Each CTA bins the
// batch's 1024 gts into a 32x32 cell CSR in its own smem, then scans 1024
// preds (rank r -> preds [r*1024, ...)) against the 3x3 cell neighborhood —
// exactly equivalent to the full argmin (matches only matter under the 16px
// threshold, and any gt within 16px of a pred lies in the 3x3 neighborhood
// of the pred's cell). Both ranks atomicMin (gt -> min pred index) into
// RANK 0's s_best (DSMEM atomic for rank 1); cluster.sync(); rank 0 gathers
// from an smem-staged pred slab.
//
// R15: the count-phase atomicAdd's RETURN VALUE is this gt's within-cell
// rank, so the scatter position is s_off[cell] + rank — plain LDS + STS, no
// second atomic pass and no cursor copy. Within-cell order changes
// (count-order vs cursor-order), but the argmin key is order-invariant, so
// the result is bit-identical.
//
// Argmin: ONE u64 min over key = (d2_bits << 32) | gi (d2 >= 0 so IEEE bits
// order as unsigned). Init key = bits(256.0f)<<32 folds the threshold:
// strict <, jnp.argmin first-index tie rule. d2 via __fadd_rn/__fmul_rn
// (no FMA contraction) -> bit-identical to the reference; rel_err == 0.0.
__global__ __launch_bounds__(1024, 1) __cluster_dims__(2, 1, 1)
void lacss_match_kernel(
    const float2* __restrict__ gt,    // [BATCH, NGT]
    const float2* __restrict__ pred,  // [BATCH, MPRED]
    float2* __restrict__ out)         // [BATCH, NGT]
{
    __shared__ int    s_cnt[NCELL];      // per-cell counts
    __shared__ int    s_off[NCELL + 1];  // exclusive CSR offsets
    __shared__ float4 s_pt[NGT];         // {gx, gy, idx-as-float, pad} binned
    __shared__ int    s_best[NGT];       // min matched pred j per gt (rank0 authoritative)
    __shared__ float2 s_pred[MPRED];     // full pred slab (rank0 authoritative)
    __shared__ int    s_wsum[32];

    cg::cluster_group cluster = cg::this_cluster();
    const unsigned rank = cluster.block_rank();

    const int b    = blockIdx.x >> 1;
    const int tid  = threadIdx.x;
    const int lane = tid & 31;
    const int wid  = tid >> 5;

    // ---- prefetch both inputs (MLP=2, DRAM latency behind binning) ----
    const int j = (int)rank * 1024 + tid;          // this thread's pred
    const float2 p = pred[b * MPRED + j];
    const float2 g = gt[b * NGT + tid];

    s_cnt[tid]  = 0;
    s_best[tid] = MPRED;                 // sentinel: unmatched
    __syncthreads();

    // ---- stage pred slab into rank0's smem (overlapped with binning;
    //      visibility at the tail via cluster.sync) ----
    {
        float2* dst = (rank == 0) ? s_pred
                                  : cluster.map_shared_rank(s_pred, 0);
        dst[j] = p;                      // disjoint ranges per rank
    }

    // ---- count (cell = y/16 * 32 + x/16; *2^-4 exact); the returned value
    //      is this gt's within-cell rank -> no second atomic pass needed ----
    const int gcell = (int)(g.y * 0.0625f) * GDIM + (int)(g.x * 0.0625f);
    const int r0 = atomicAdd(&s_cnt[gcell], 1);
    __syncthreads();

    // ---- exclusive prefix sum of s_cnt -> s_off ----
    int v   = s_cnt[tid];
    int inc = v;
    #pragma unroll
    for (int d = 1; d < 32; d <<= 1) {
        int n = __shfl_up_sync(0xFFFFFFFFu, inc, d);
        if (lane >= d) inc += n;
    }
    if (lane == 31) s_wsum[wid] = inc;
    __syncthreads();
    if (wid == 0) {
        int w  = s_wsum[lane];
        int wi = w;
        #pragma unroll
        for (int d = 1; d < 32; d <<= 1) {
            int n = __shfl_up_sync(0xFFFFFFFFu, wi, d);
            if (lane >= d) wi += n;
        }
        s_wsum[lane] = wi - w;           // exclusive offset of warp `lane`
    }
    __syncthreads();
    s_off[tid] = (inc - v) + s_wsum[wid];
    if (tid == 0) s_off[NCELL] = NGT;
    __syncthreads();

    // ---- scatter: position = CSR offset + count-phase rank (plain STS) ----
    s_pt[s_off[gcell] + r0] = make_float4(g.x, g.y, __int_as_float(tid), 0.f);
    __syncthreads();

    // ---- pred phase: one pred per thread, 3x3 neighborhood (3 runs),
    //      selection = single u64 min over (d2_bits, gi) ----
    {
        const int pcx = (int)(p.x * 0.0625f);
        const int pcy = (int)(p.y * 0.0625f);
        const int x0 = max(pcx - 1, 0), x1 = min(pcx + 1, GDIM - 1);
        const int y0 = max(pcy - 1, 0), y1 = min(pcy + 1, GDIM - 1);

        const unsigned long long K0 =
            ((unsigned long long)__float_as_uint(THRESH2)) << 32;
        unsigned long long best = K0;

        for (int cy = y0; cy <= y1; cy++) {
            const int ks = s_off[cy * GDIM + x0];
            const int ke = s_off[cy * GDIM + x1 + 1];   // cells contiguous in x
            for (int k = ks; k < ke; k++) {
                float4 q = s_pt[k];                     // one LDS.128
                float dx = __fadd_rn(p.x, -q.x);
                float dy = __fadd_rn(p.y, -q.y);
                float d2 = __fadd_rn(__fmul_rn(dx, dx), __fmul_rn(dy, dy));
                unsigned int bits = __float_as_uint(d2);
                unsigned int gi   = (unsigned int)__float_as_int(q.z);
                unsigned long long key;
                asm("mov.b64 %0, {%1, %2};" : "=l"(key) : "r"(gi), "r"(bits));
                best = (key < best) ? key : best;
            }
        }

        if (best < K0) {
            int bi = (int)(unsigned int)best;           // low word = gt index
            int* dst = (rank == 0) ? s_best
                                   : cluster.map_shared_rank(s_best, 0);
            atomicMin(&dst[bi], j);
        }
    }

    cluster.sync();                      // orders remote atomics + s_pred stores

    // ---- fused gather by rank 0: pure-SMEM reads ----
    if (rank == 0) {
        const int s = s_best[tid];
        out[b * NGT + tid] = (s < MPRED) ? s_pred[s] : g;
    }
}

extern "C" void kernel_launch(void* const* d_in, const int* in_sizes, int n_in,
                              void* d_out, int out_size) {
    const float2* gt   = (const float2*)d_in[0];   // gt_locations   [64,1024,2] f32
    const float2* pred = (const float2*)d_in[1];   // pred_locations [64,2048,2] f32
    float2* out = (float2*)d_out;                  // [64,1024,2] f32

    lacss_match_kernel<<<BATCH * 2, 1024>>>(gt, pred, out);
}